// round 5
// baseline (speedup 1.0000x reference)
#include <cuda_runtime.h>

// 3x3 conv, stride 1, pad 1, single channel, X: (32, 1024, 1024) fp32.
// 2x4 register tile per thread + depth-1 double-buffered row prefetch.
// Tiny register footprint (~32) -> 8 CTAs/SM, ~90%+ occupancy: maximize
// warp-level latency tolerance (R1..R4 showed occupancy, not per-thread MLP,
// is what moves DRAM utilization on this streaming stencil).
// Block = 256 threads covers 2 rows x 1024 cols. Grid = 32 * 512 = 16384.

#define IMG_W 1024
#define IMG_H 1024

__global__ __launch_bounds__(256, 8) void conv3x3_kernel(
    const float* __restrict__ X,
    const float* __restrict__ Wt,
    float* __restrict__ Y)
{
    const int tid   = threadIdx.x;
    const int bx    = blockIdx.x;
    const int batch = bx >> 9;        // / 512 row-pairs
    const int rg    = bx & 511;
    const int r0    = rg << 1;        // first output row of this thread's tile
    const int c0    = tid << 2;       // first output col (float4 aligned)

    const size_t plane = (size_t)IMG_W * IMG_H;
    const float* Xb = X + (size_t)batch * plane;
    float*       Yb = Y + (size_t)batch * plane;

    float w[9];
#pragma unroll
    for (int i = 0; i < 9; i++) w[i] = __ldg(Wt + i);

    float acc[2][4];
#pragma unroll
    for (int i = 0; i < 2; i++)
#pragma unroll
        for (int j = 0; j < 4; j++) acc[i][j] = 0.0f;

    // Double-buffered row registers: cols c0-1 .. c0+4.
    float rowbuf[2][6];

#define LOAD_ROW(s, r)                                                        \
    do {                                                                      \
        if ((r) >= 0 && (r) < IMG_H) {                                        \
            const float* p = Xb + (size_t)(r) * IMG_W + c0;                   \
            const float4 v = *reinterpret_cast<const float4*>(p);             \
            rowbuf[s][1] = v.x; rowbuf[s][2] = v.y;                           \
            rowbuf[s][3] = v.z; rowbuf[s][4] = v.w;                           \
            rowbuf[s][0] = (c0 > 0)         ? __ldg(p - 1) : 0.0f;            \
            rowbuf[s][5] = (c0 + 4 < IMG_W) ? __ldg(p + 4) : 0.0f;            \
        } else {                                                              \
            rowbuf[s][0] = 0.0f; rowbuf[s][1] = 0.0f; rowbuf[s][2] = 0.0f;    \
            rowbuf[s][3] = 0.0f; rowbuf[s][4] = 0.0f; rowbuf[s][5] = 0.0f;    \
        }                                                                     \
    } while (0)

    // Prime the pipeline with the first row (rr = -1).
    LOAD_ROW(0, r0 - 1);

    // Stream rows rr = -1 .. 2; prefetch rr+1 before computing rr.
#pragma unroll
    for (int rr = -1; rr <= 2; rr++) {
        const int cur = (rr + 1) & 1;
        const int nxt = (rr + 2) & 1;
        if (rr < 2) {
            LOAD_ROW(nxt, r0 + rr + 1);
        }

        // Output row i (0..1) uses input rows r0+i-1..r0+i+1 -> ky = rr-i+1.
#pragma unroll
        for (int i = 0; i < 2; i++) {
            const int ky = rr - i + 1;
            if (ky >= 0 && ky <= 2) {   // compile-time after unroll
#pragma unroll
                for (int j = 0; j < 4; j++) {
                    acc[i][j] = fmaf(w[ky * 3 + 0], rowbuf[cur][j],
                                fmaf(w[ky * 3 + 1], rowbuf[cur][j + 1],
                                fmaf(w[ky * 3 + 2], rowbuf[cur][j + 2],
                                     acc[i][j])));
                }
            }
        }
    }
#undef LOAD_ROW

#pragma unroll
    for (int i = 0; i < 2; i++) {
        float4 o;
        o.x = acc[i][0]; o.y = acc[i][1]; o.z = acc[i][2]; o.w = acc[i][3];
        *reinterpret_cast<float4*>(Yb + (size_t)(r0 + i) * IMG_W + c0) = o;
    }
}

extern "C" void kernel_launch(void* const* d_in, const int* in_sizes, int n_in,
                              void* d_out, int out_size)
{
    const float* X  = (const float*)d_in[0];   // (32, 1024, 1024) fp32
    const float* Wt = (const float*)d_in[1];   // (3, 3) fp32
    float* Y        = (float*)d_out;           // (32, 1024, 1024) fp32

    const int grid = 32 * 512;                 // batches * 2-row groups
    conv3x3_kernel<<<grid, 256>>>(X, Wt, Y);
}

// round 6
// speedup vs baseline: 1.1404x; 1.1404x over previous
#include <cuda_runtime.h>

// 3x3 conv, stride 1, pad 1, single channel, X: (32, 1024, 1024) fp32.
// R3 structure (4x4 tile, depth-1 double-buffered row prefetch, occ ~64%)
// with halo loads replaced by warp shuffles: each thread issues ONE float4
// per input row; left/right halo come from neighbor lanes via shfl at
// consume time. Only lanes 0/31 do a predicated scalar edge load.
// Cuts L1tex wavefronts per row from ~12 to ~4-6 per warp.

#define IMG_W 1024
#define IMG_H 1024

__global__ __launch_bounds__(256, 6) void conv3x3_kernel(
    const float* __restrict__ X,
    const float* __restrict__ Wt,
    float* __restrict__ Y)
{
    const int tid   = threadIdx.x;
    const int lane  = tid & 31;
    const int bx    = blockIdx.x;
    const int batch = bx >> 8;        // / 256 row-groups
    const int rg    = bx & 255;
    const int r0    = rg << 2;        // first output row of this thread's tile
    const int c0    = tid << 2;       // first output col (float4 aligned)

    const size_t plane = (size_t)IMG_W * IMG_H;
    const float* Xb = X + (size_t)batch * plane;
    float*       Yb = Y + (size_t)batch * plane;

    float w[9];
#pragma unroll
    for (int i = 0; i < 9; i++) w[i] = __ldg(Wt + i);

    float acc[4][4];
#pragma unroll
    for (int i = 0; i < 4; i++)
#pragma unroll
        for (int j = 0; j < 4; j++) acc[i][j] = 0.0f;

    // Double-buffered rows: 4 interior floats + 2 edge scalars (valid only
    // on lanes 0 / 31 respectively).
    float rowbuf[2][4];
    float edgeL[2], edgeR[2];

    // r is warp-uniform (all threads share r0), so the branch is uniform and
    // the shuffles at consume time are safe.
#define LOAD_ROW(s, r)                                                        \
    do {                                                                      \
        if ((r) >= 0 && (r) < IMG_H) {                                        \
            const float* p = Xb + (size_t)(r) * IMG_W + c0;                   \
            const float4 v = *reinterpret_cast<const float4*>(p);             \
            rowbuf[s][0] = v.x; rowbuf[s][1] = v.y;                           \
            rowbuf[s][2] = v.z; rowbuf[s][3] = v.w;                           \
            edgeL[s] = (lane == 0  && c0 > 0)          ? __ldg(p - 1) : 0.0f; \
            edgeR[s] = (lane == 31 && c0 + 4 < IMG_W)  ? __ldg(p + 4) : 0.0f; \
        } else {                                                              \
            rowbuf[s][0] = 0.0f; rowbuf[s][1] = 0.0f;                         \
            rowbuf[s][2] = 0.0f; rowbuf[s][3] = 0.0f;                         \
            edgeL[s] = 0.0f; edgeR[s] = 0.0f;                                 \
        }                                                                     \
    } while (0)

    // Prime the pipeline with the first row (rr = -1).
    LOAD_ROW(0, r0 - 1);

    // Stream rows rr = -1 .. 4; prefetch rr+1 before computing rr.
#pragma unroll
    for (int rr = -1; rr <= 4; rr++) {
        const int cur = (rr + 1) & 1;
        const int nxt = (rr + 2) & 1;
        if (rr < 4) {
            LOAD_ROW(nxt, r0 + rr + 1);
        }

        // Assemble the 6-wide window for row rr via shuffles.
        float row[6];
        row[1] = rowbuf[cur][0];
        row[2] = rowbuf[cur][1];
        row[3] = rowbuf[cur][2];
        row[4] = rowbuf[cur][3];
        float left  = __shfl_up_sync(0xFFFFFFFFu,  row[4], 1);
        float right = __shfl_down_sync(0xFFFFFFFFu, row[1], 1);
        if (lane == 0)  left  = edgeL[cur];
        if (lane == 31) right = edgeR[cur];
        row[0] = left;
        row[5] = right;

        // Output row i (0..3) uses input rows r0+i-1..r0+i+1 -> ky = rr-i+1.
#pragma unroll
        for (int i = 0; i < 4; i++) {
            const int ky = rr - i + 1;
            if (ky >= 0 && ky <= 2) {   // compile-time after unroll
#pragma unroll
                for (int j = 0; j < 4; j++) {
                    acc[i][j] = fmaf(w[ky * 3 + 0], row[j],
                                fmaf(w[ky * 3 + 1], row[j + 1],
                                fmaf(w[ky * 3 + 2], row[j + 2],
                                     acc[i][j])));
                }
            }
        }
    }
#undef LOAD_ROW

#pragma unroll
    for (int i = 0; i < 4; i++) {
        float4 o;
        o.x = acc[i][0]; o.y = acc[i][1]; o.z = acc[i][2]; o.w = acc[i][3];
        *reinterpret_cast<float4*>(Yb + (size_t)(r0 + i) * IMG_W + c0) = o;
    }
}

extern "C" void kernel_launch(void* const* d_in, const int* in_sizes, int n_in,
                              void* d_out, int out_size)
{
    const float* X  = (const float*)d_in[0];   // (32, 1024, 1024) fp32
    const float* Wt = (const float*)d_in[1];   // (3, 3) fp32
    float* Y        = (float*)d_out;           // (32, 1024, 1024) fp32

    const int grid = 32 * 256;                 // batches * 4-row groups
    conv3x3_kernel<<<grid, 256>>>(X, Wt, Y);
}